// round 14
// baseline (speedup 1.0000x reference)
#include <cuda_runtime.h>
#include <cuda_fp16.h>
#include <math.h>
#include <stdint.h>

#define BATCH 4
#define SEQ   2048
#define DM    1024
#define DFF   4096
#define NHEAD 16
#define HD    64
#define NROWS (BATCH*SEQ)   /* 8192 */

// ---------------- scratch (device globals; no allocation allowed) ----------
__device__ __half g_xn   [(size_t)NROWS * DM];        // LN out (half)
__device__ __half g_qkvh [(size_t)NROWS * 3 * DM];    // qkv (half)
__device__ __half g_attnh[(size_t)NROWS * DM];        // attention out (half)
__device__ float  g_res1 [(size_t)NROWS * DM];
__device__ __half g_ff   [(size_t)NROWS * DFF];       // gelu out (half)
// transposed (N-major, K-contig) half weights
__device__ __half g_wqkvT[(size_t)3 * DM * DM];
__device__ __half g_woutT[(size_t)DM * DM];
__device__ __half g_wfc1T[(size_t)DFF * DM];
__device__ __half g_wfc2T[(size_t)DM * DFF];

// ---------------- helpers ---------------------------------------------------
__device__ __forceinline__ void cpa16(uint32_t dst, const void* src) {
    asm volatile("cp.async.cg.shared.global [%0], [%1], 16;" :: "r"(dst), "l"(src));
}
#define CP_COMMIT() asm volatile("cp.async.commit_group;" ::: "memory")
#define CP_WAIT(n)  asm volatile("cp.async.wait_group %0;" :: "n"(n) : "memory")

__device__ __forceinline__ uint32_t smem_u32(const void* p) {
    uint32_t a;
    asm("{ .reg .u64 t; cvta.to.shared.u64 t, %1; cvt.u32.u64 %0, t; }" : "=r"(a) : "l"(p));
    return a;
}
__device__ __forceinline__ float gelu_f(float x) {
    float x3 = x * x * x;
    return 0.5f * x * (1.0f + tanhf(0.7978845608028654f * (x + 0.044715f * x3)));
}

#define LDSM4(r0, r1, r2, r3, addr) \
    asm volatile("ldmatrix.sync.aligned.m8n8.x4.shared.b16 {%0,%1,%2,%3}, [%4];" \
        : "=r"(r0), "=r"(r1), "=r"(r2), "=r"(r3) : "r"(addr))
#define LDSM4T(r0, r1, r2, r3, addr) \
    asm volatile("ldmatrix.sync.aligned.m8n8.x4.trans.shared.b16 {%0,%1,%2,%3}, [%4];" \
        : "=r"(r0), "=r"(r1), "=r"(r2), "=r"(r3) : "r"(addr))

#define MMA_F16(c, a0,a1,a2,a3, b0,b1)                                      \
    asm volatile(                                                           \
        "mma.sync.aligned.m16n8k16.row.col.f32.f16.f16.f32 "                \
        "{%0,%1,%2,%3}, {%4,%5,%6,%7}, {%8,%9}, {%0,%1,%2,%3};\n"           \
        : "+f"((c)[0]), "+f"((c)[1]), "+f"((c)[2]), "+f"((c)[3])            \
        : "r"(a0), "r"(a1), "r"(a2), "r"(a3), "r"(b0), "r"(b1))

// ---------------- weight transpose -> half, K-contiguous --------------------
__global__ __launch_bounds__(256) void transpose_h(
    const float* __restrict__ in, __half* __restrict__ out, int K, int N)
{
    __shared__ float s[32 * 33];
    int t = threadIdx.x;
    int n0 = blockIdx.x * 32, k0 = blockIdx.y * 32;
    int r = t >> 3, c = (t & 7) * 4;
    float4 v = *(const float4*)(in + (size_t)(k0 + r) * N + n0 + c);
    s[(c + 0) * 33 + r] = v.x;
    s[(c + 1) * 33 + r] = v.y;
    s[(c + 2) * 33 + r] = v.z;
    s[(c + 3) * 33 + r] = v.w;
    __syncthreads();
    __half2 h0 = __floats2half2_rn(s[r * 33 + c + 0], s[r * 33 + c + 1]);
    __half2 h1 = __floats2half2_rn(s[r * 33 + c + 2], s[r * 33 + c + 3]);
    __half* op = out + (size_t)(n0 + r) * K + k0 + c;
    *(__half2*)(op)     = h0;
    *(__half2*)(op + 2) = h1;
}

// ---------------- LayerNorm (outputs half) ----------------------------------
__global__ __launch_bounds__(256) void ln_kernel(
    const float* __restrict__ x, const float* __restrict__ scale,
    const float* __restrict__ bias, __half* __restrict__ out)
{
    int row = blockIdx.x;
    const float4* xr = (const float4*)(x + (size_t)row * DM);
    float4 v = xr[threadIdx.x];
    float s  = v.x + v.y + v.z + v.w;
    float ss = v.x*v.x + v.y*v.y + v.z*v.z + v.w*v.w;
    #pragma unroll
    for (int o = 16; o > 0; o >>= 1) {
        s  += __shfl_xor_sync(0xffffffffu, s,  o);
        ss += __shfl_xor_sync(0xffffffffu, ss, o);
    }
    __shared__ float smS[8], smSS[8];
    __shared__ float sMean, sRstd;
    int w = threadIdx.x >> 5, lane = threadIdx.x & 31;
    if (lane == 0) { smS[w] = s; smSS[w] = ss; }
    __syncthreads();
    if (threadIdx.x == 0) {
        float S = 0.f, SS = 0.f;
        #pragma unroll
        for (int i = 0; i < 8; i++) { S += smS[i]; SS += smSS[i]; }
        float mean = S * (1.0f / DM);
        float var  = SS * (1.0f / DM) - mean * mean;
        sMean = mean; sRstd = rsqrtf(var + 1e-6f);
    }
    __syncthreads();
    float mean = sMean, rstd = sRstd;
    int c = threadIdx.x * 4;
    float4 sc = *(const float4*)(scale + c);
    float4 bi = *(const float4*)(bias  + c);
    __half2 h0 = __floats2half2_rn((v.x - mean) * rstd * sc.x + bi.x,
                                   (v.y - mean) * rstd * sc.y + bi.y);
    __half2 h1 = __floats2half2_rn((v.z - mean) * rstd * sc.z + bi.z,
                                   (v.w - mean) * rstd * sc.w + bi.w);
    __half* op = out + (size_t)row * DM + c;
    *(__half2*)(op)     = h0;
    *(__half2*)(op + 2) = h1;
}

// ---------------- FP16 mma.sync GEMM: 256x128 tile, 512 thr, 3 stages -------
// epi: 0 = bias -> half, 1 = bias + residual -> fp32, 2 = gelu(bias) -> half
#define HROWB 80
#define HSTGB ((256 + 128) * HROWB)    /* 30720 B per stage */
#define HGSM  (3 * HSTGB)              /* 92160 B */
#define BOFF  (256 * HROWB)            /* B region offset inside stage */

__global__ __launch_bounds__(512, 1) void gemm_f16(
    const __half* __restrict__ A, const __half* __restrict__ Bt,
    const float* __restrict__ bias, const float* __restrict__ R,
    float* __restrict__ C, __half* __restrict__ Ch,
    int M, int N, int K, int epi)
{
    extern __shared__ char smc[];
    const uint32_t sb = smem_u32(smc);

    const int t  = threadIdx.x;
    const int m0 = blockIdx.y * 256, n0 = blockIdx.x * 128;
    const int w  = t >> 5, lane = t & 31;
    const int wr = w >> 2, wc = w & 3;        // 4 x 4 warps
    const int wm = wr * 64, wn = wc * 32;     // warp tile 64x32
    const int lr = lane >> 2, lc = lane & 3;

    float c[4][4][4];
    #pragma unroll
    for (int mf = 0; mf < 4; mf++)
        #pragma unroll
        for (int nf = 0; nf < 4; nf++)
            #pragma unroll
            for (int i = 0; i < 4; i++) c[mf][nf][i] = 0.f;

    // loader: A rows t>>2 and t>>2+128 (granule t&3), B row t>>2 (granule t&3)
    const int row = t >> 2, kg = t & 3;
    const __half* Ap0 = A  + (size_t)(m0 + row)       * K + kg * 8;
    const __half* Ap1 = A  + (size_t)(m0 + 128 + row) * K + kg * 8;
    const __half* Bp0 = Bt + (size_t)(n0 + row)       * K + kg * 8;
    const uint32_t dA0 = sb + row * HROWB + kg * 16;
    const uint32_t dA1 = sb + (row + 128) * HROWB + kg * 16;
    const uint32_t dB0 = sb + BOFF + row * HROWB + kg * 16;

    const int NC = K >> 5;

    #define LOAD_STAGE(st, cc) do {                                   \
        uint32_t so_ = (uint32_t)(st) * HSTGB;                        \
        size_t ko_ = (size_t)(cc) << 5;                               \
        cpa16(dA0 + so_, Ap0 + ko_);                                  \
        cpa16(dA1 + so_, Ap1 + ko_);                                  \
        cpa16(dB0 + so_, Bp0 + ko_);                                  \
        CP_COMMIT();                                                  \
    } while (0)

    LOAD_STAGE(0, 0);
    LOAD_STAGE(1, 1);

    const int lm_r = lane & 15;
    const int lm_k = (lane >> 4) * 16;

    int st = 0;
    for (int cc = 0; cc < NC; cc++) {
        CP_WAIT(1);
        __syncthreads();
        // stage (st+2)%3 was fully consumed in iteration cc-1 (proven by the
        // barrier above) -> safe to refill now, overlapping with our MMAs.
        if (cc + 2 < NC) LOAD_STAGE((st + 2) % 3, cc + 2);
        else             CP_COMMIT();

        const uint32_t as = sb + st * HSTGB;
        const uint32_t bs = as + BOFF;
        #pragma unroll
        for (int ks = 0; ks < 2; ks++) {
            uint32_t af[4][4];
            #pragma unroll
            for (int mf = 0; mf < 4; mf++) {
                uint32_t addr = as + (wm + mf * 16 + lm_r) * HROWB + ks * 32 + lm_k;
                LDSM4(af[mf][0], af[mf][1], af[mf][2], af[mf][3], addr);
            }
            uint32_t bf[4][2];
            #pragma unroll
            for (int np = 0; np < 2; np++) {
                uint32_t r0, r1, r2, r3;
                uint32_t addr = bs + (wn + np * 16 + lm_r) * HROWB + ks * 32 + lm_k;
                LDSM4(r0, r1, r2, r3, addr);
                bf[np * 2 + 0][0] = r0; bf[np * 2 + 0][1] = r2;
                bf[np * 2 + 1][0] = r1; bf[np * 2 + 1][1] = r3;
            }
            #pragma unroll
            for (int mf = 0; mf < 4; mf++)
                #pragma unroll
                for (int nf = 0; nf < 4; nf++)
                    MMA_F16(c[mf][nf], af[mf][0], af[mf][1], af[mf][2], af[mf][3],
                            bf[nf][0], bf[nf][1]);
        }
        st = (st + 1) % 3;
    }
    #undef LOAD_STAGE

    // -------- epilogue --------
    #pragma unroll
    for (int mf = 0; mf < 4; mf++) {
        #pragma unroll
        for (int nf = 0; nf < 4; nf++) {
            int rowg = m0 + wm + mf * 16 + lr;
            int col  = n0 + wn + nf * 8 + lc * 2;
            float b0 = bias[col], b1 = bias[col + 1];
            float v0 = c[mf][nf][0] + b0;
            float v1 = c[mf][nf][1] + b1;
            float v2 = c[mf][nf][2] + b0;
            float v3 = c[mf][nf][3] + b1;
            if (epi == 1) {
                const float* r0 = R + (size_t)rowg * N + col;
                const float* r1 = R + (size_t)(rowg + 8) * N + col;
                v0 += r0[0]; v1 += r0[1];
                v2 += r1[0]; v3 += r1[1];
                *(float2*)(C + (size_t)rowg * N + col)       = make_float2(v0, v1);
                *(float2*)(C + (size_t)(rowg + 8) * N + col) = make_float2(v2, v3);
            } else if (epi == 2) {
                *(__half2*)(Ch + (size_t)rowg * N + col) =
                    __floats2half2_rn(gelu_f(v0), gelu_f(v1));
                *(__half2*)(Ch + (size_t)(rowg + 8) * N + col) =
                    __floats2half2_rn(gelu_f(v2), gelu_f(v3));
            } else {
                *(__half2*)(Ch + (size_t)rowg * N + col) =
                    __floats2half2_rn(v0, v1);
                *(__half2*)(Ch + (size_t)(rowg + 8) * N + col) =
                    __floats2half2_rn(v2, v3);
            }
        }
    }
}

// ---------------- Flash-attention, fp16 mma + ldmatrix (causal) -------------
// BQ=128, BK=64, 8 warps (16 q-rows each).  grid (SEQ/128, BATCH*NHEAD).
#define AH 72
#define ATTN_SM_BYTES ((128*AH + 64*AH + 64*AH + 128*AH) * 2)  /* 55296 */

__global__ __launch_bounds__(256) void attn_f16()
{
    extern __shared__ __half smh[];
    __half* Qs = smh;
    __half* Ks = Qs + 128 * AH;
    __half* Vs = Ks + 64 * AH;
    __half* Ps = Vs + 64 * AH;
    const uint32_t sQ = smem_u32(Qs), sK = smem_u32(Ks),
                   sV = smem_u32(Vs), sP = smem_u32(Ps);

    const int t = threadIdx.x, w = t >> 5, lane = t & 31;
    const int lr = lane >> 2, lc = lane & 3;
    const int lm_r = lane & 15, lm_c = (lane >> 4) * 8;
    const int qt = blockIdx.x, bh = blockIdx.y;
    const int b = bh >> 4, h = bh & 15;
    const size_t baseBH = (size_t)b * SEQ * (3 * DM) + (size_t)h * HD;
    const int q0 = qt * 128;
    const int wm = w * 16;

    const __half2 hscale = __floats2half2_rn(0.125f, 0.125f);
    for (int i = t; i < 128 * 8; i += 256) {
        int r = i >> 3, g = i & 7;
        uint4 v = *(const uint4*)&g_qkvh[baseBH + (size_t)(q0 + r) * (3 * DM) + g * 8];
        __half2* hp = (__half2*)&v;
        hp[0] = __hmul2(hp[0], hscale);
        hp[1] = __hmul2(hp[1], hscale);
        hp[2] = __hmul2(hp[2], hscale);
        hp[3] = __hmul2(hp[3], hscale);
        *(uint4*)&Qs[r * AH + g * 8] = v;
    }

    float o[8][4];
    #pragma unroll
    for (int nf = 0; nf < 8; nf++)
        #pragma unroll
        for (int i = 0; i < 4; i++) o[nf][i] = 0.f;
    float m0v = -1e30f, m1v = -1e30f, l0 = 0.f, l1 = 0.f;

    const int ntile = (q0 + 128) / 64;
    for (int kt = 0; kt < ntile; kt++) {
        int k0 = kt * 64;
        for (int i = t; i < 64 * 8; i += 256) {
            int r = i >> 3, g = i & 7;
            size_t base = baseBH + (size_t)(k0 + r) * (3 * DM);
            *(uint4*)&Ks[r * AH + g * 8] = *(const uint4*)&g_qkvh[base + DM + g * 8];
            *(uint4*)&Vs[r * AH + g * 8] = *(const uint4*)&g_qkvh[base + 2 * DM + g * 8];
        }
        __syncthreads();

        float s[8][4];
        #pragma unroll
        for (int nf = 0; nf < 8; nf++)
            #pragma unroll
            for (int i = 0; i < 4; i++) s[nf][i] = 0.f;
        #pragma unroll
        for (int ks = 0; ks < 4; ks++) {
            uint32_t a0, a1, a2, a3;
            LDSM4(a0, a1, a2, a3,
                  sQ + ((wm + lm_r) * AH + ks * 16 + lm_c) * 2);
            #pragma unroll
            for (int np = 0; np < 4; np++) {
                uint32_t r0, r1, r2, r3;
                LDSM4(r0, r1, r2, r3,
                      sK + ((np * 16 + lm_r) * AH + ks * 16 + lm_c) * 2);
                MMA_F16(s[np * 2 + 0], a0, a1, a2, a3, r0, r2);
                MMA_F16(s[np * 2 + 1], a0, a1, a2, a3, r1, r3);
            }
        }

        if (k0 + 63 > q0 + wm) {
            int qi0 = q0 + wm + lr, qi1 = qi0 + 8;
            #pragma unroll
            for (int nf = 0; nf < 8; nf++) {
                int kj0 = k0 + nf * 8 + 2 * lc, kj1 = kj0 + 1;
                if (kj0 > qi0) s[nf][0] = -1e30f;
                if (kj1 > qi0) s[nf][1] = -1e30f;
                if (kj0 > qi1) s[nf][2] = -1e30f;
                if (kj1 > qi1) s[nf][3] = -1e30f;
            }
        }

        float mt0 = -1e30f, mt1 = -1e30f;
        #pragma unroll
        for (int nf = 0; nf < 8; nf++) {
            mt0 = fmaxf(mt0, fmaxf(s[nf][0], s[nf][1]));
            mt1 = fmaxf(mt1, fmaxf(s[nf][2], s[nf][3]));
        }
        mt0 = fmaxf(mt0, __shfl_xor_sync(0xffffffffu, mt0, 1));
        mt0 = fmaxf(mt0, __shfl_xor_sync(0xffffffffu, mt0, 2));
        mt1 = fmaxf(mt1, __shfl_xor_sync(0xffffffffu, mt1, 1));
        mt1 = fmaxf(mt1, __shfl_xor_sync(0xffffffffu, mt1, 2));
        float mn0 = fmaxf(m0v, mt0), mn1 = fmaxf(m1v, mt1);
        float scl0 = __expf(m0v - mn0), scl1 = __expf(m1v - mn1);
        m0v = mn0; m1v = mn1;
        float ls0 = 0.f, ls1 = 0.f;
        #pragma unroll
        for (int nf = 0; nf < 8; nf++) {
            float p0 = __expf(s[nf][0] - mn0);
            float p1 = __expf(s[nf][1] - mn0);
            float p2 = __expf(s[nf][2] - mn1);
            float p3 = __expf(s[nf][3] - mn1);
            s[nf][0] = p0; s[nf][1] = p1; s[nf][2] = p2; s[nf][3] = p3;
            ls0 += p0 + p1; ls1 += p2 + p3;
        }
        ls0 += __shfl_xor_sync(0xffffffffu, ls0, 1);
        ls0 += __shfl_xor_sync(0xffffffffu, ls0, 2);
        ls1 += __shfl_xor_sync(0xffffffffu, ls1, 1);
        ls1 += __shfl_xor_sync(0xffffffffu, ls1, 2);
        l0 = l0 * scl0 + ls0;
        l1 = l1 * scl1 + ls1;
        #pragma unroll
        for (int nf = 0; nf < 8; nf++) {
            o[nf][0] *= scl0; o[nf][1] *= scl0;
            o[nf][2] *= scl1; o[nf][3] *= scl1;
        }

        #pragma unroll
        for (int nf = 0; nf < 8; nf++) {
            *(__half2*)&Ps[(wm + lr) * AH + nf * 8 + 2 * lc] =
                __floats2half2_rn(s[nf][0], s[nf][1]);
            *(__half2*)&Ps[(wm + lr + 8) * AH + nf * 8 + 2 * lc] =
                __floats2half2_rn(s[nf][2], s[nf][3]);
        }
        __syncwarp();

        #pragma unroll
        for (int ks = 0; ks < 4; ks++) {
            uint32_t a0, a1, a2, a3;
            LDSM4(a0, a1, a2, a3,
                  sP + ((wm + lm_r) * AH + ks * 16 + lm_c) * 2);
            #pragma unroll
            for (int dp = 0; dp < 4; dp++) {
                uint32_t r0, r1, r2, r3;
                LDSM4T(r0, r1, r2, r3,
                       sV + ((ks * 16 + lm_r) * AH + dp * 16 + lm_c) * 2);
                MMA_F16(o[dp * 2 + 0], a0, a1, a2, a3, r0, r1);
                MMA_F16(o[dp * 2 + 1], a0, a1, a2, a3, r2, r3);
            }
        }
        __syncthreads();
    }

    float il0 = 1.0f / l0, il1 = 1.0f / l1;
    int row0 = q0 + wm + lr, row1 = row0 + 8;
    #pragma unroll
    for (int nf = 0; nf < 8; nf++) {
        int col = h * HD + nf * 8 + 2 * lc;
        *(__half2*)&g_attnh[(size_t)(b * SEQ + row0) * DM + col] =
            __floats2half2_rn(o[nf][0] * il0, o[nf][1] * il0);
        *(__half2*)&g_attnh[(size_t)(b * SEQ + row1) * DM + col] =
            __floats2half2_rn(o[nf][2] * il1, o[nf][3] * il1);
    }
}

// ---------------- launch ---------------------------------------------------
extern "C" void kernel_launch(void* const* d_in, const int* in_sizes, int n_in,
                              void* d_out, int out_size)
{
    (void)in_sizes; (void)n_in; (void)out_size;
    const float* x     = (const float*)d_in[0];
    const float* w_qkv = (const float*)d_in[1];
    const float* b_qkv = (const float*)d_in[2];
    const float* w_out = (const float*)d_in[3];
    const float* b_out = (const float*)d_in[4];
    const float* w_fc1 = (const float*)d_in[5];
    const float* b_fc1 = (const float*)d_in[6];
    const float* w_fc2 = (const float*)d_in[7];
    const float* b_fc2 = (const float*)d_in[8];
    const float* ln1s  = (const float*)d_in[9];
    const float* ln1b  = (const float*)d_in[10];
    const float* ln2s  = (const float*)d_in[11];
    const float* ln2b  = (const float*)d_in[12];
    float* out = (float*)d_out;

    __half *xn, *qkvh, *attnh, *ff, *wqkvT, *woutT, *wfc1T, *wfc2T;
    float *res1;
    cudaGetSymbolAddress((void**)&xn,    g_xn);
    cudaGetSymbolAddress((void**)&qkvh,  g_qkvh);
    cudaGetSymbolAddress((void**)&attnh, g_attnh);
    cudaGetSymbolAddress((void**)&res1,  g_res1);
    cudaGetSymbolAddress((void**)&ff,    g_ff);
    cudaGetSymbolAddress((void**)&wqkvT, g_wqkvT);
    cudaGetSymbolAddress((void**)&woutT, g_woutT);
    cudaGetSymbolAddress((void**)&wfc1T, g_wfc1T);
    cudaGetSymbolAddress((void**)&wfc2T, g_wfc2T);

    cudaFuncSetAttribute(gemm_f16,
        cudaFuncAttributeMaxDynamicSharedMemorySize, HGSM);
    cudaFuncSetAttribute(attn_f16,
        cudaFuncAttributeMaxDynamicSharedMemorySize, ATTN_SM_BYTES);

    // 0. weight transposes (half, K-contiguous)
    transpose_h<<<dim3(3 * DM / 32, DM / 32), 256>>>(w_qkv, wqkvT, DM, 3 * DM);
    transpose_h<<<dim3(DM / 32, DM / 32), 256>>>(w_out, woutT, DM, DM);
    transpose_h<<<dim3(DFF / 32, DM / 32), 256>>>(w_fc1, wfc1T, DM, DFF);
    transpose_h<<<dim3(DM / 32, DFF / 32), 256>>>(w_fc2, wfc2T, DFF, DM);

    // 1. LN1 -> half
    ln_kernel<<<NROWS, 256>>>(x, ln1s, ln1b, xn);
    // 2. QKV projection -> half
    gemm_f16<<<dim3(3 * DM / 128, NROWS / 256), 512, HGSM>>>(
        xn, wqkvT, b_qkv, (const float*)0, (float*)0, qkvh,
        NROWS, 3 * DM, DM, 0);
    // 3. causal flash attention (fp16 mma) -> half
    attn_f16<<<dim3(SEQ / 128, BATCH * NHEAD), 256, ATTN_SM_BYTES>>>();
    // 4. out projection + residual(x) -> fp32
    gemm_f16<<<dim3(DM / 128, NROWS / 256), 512, HGSM>>>(
        attnh, woutT, b_out, x, res1, (__half*)0, NROWS, DM, DM, 1);
    // 5. LN2 -> half
    ln_kernel<<<NROWS, 256>>>(res1, ln2s, ln2b, xn);
    // 6. FC1 + gelu -> half
    gemm_f16<<<dim3(DFF / 128, NROWS / 256), 512, HGSM>>>(
        xn, wfc1T, b_fc1, (const float*)0, (float*)0, ff, NROWS, DFF, DM, 2);
    // 7. FC2 + residual(res1) -> fp32 out
    gemm_f16<<<dim3(DM / 128, NROWS / 256), 512, HGSM>>>(
        ff, wfc2T, b_fc2, res1, out, (__half*)0, NROWS, DM, DFF, 1);
}

// round 16
// speedup vs baseline: 1.0497x; 1.0497x over previous
#include <cuda_runtime.h>
#include <cuda_fp16.h>
#include <math.h>
#include <stdint.h>

#define BATCH 4
#define SEQ   2048
#define DM    1024
#define DFF   4096
#define NHEAD 16
#define HD    64
#define NROWS (BATCH*SEQ)   /* 8192 */

// ---------------- scratch (device globals; no allocation allowed) ----------
__device__ __half g_xn   [(size_t)NROWS * DM];        // LN out (half)
__device__ __half g_qkvh [(size_t)NROWS * 3 * DM];    // qkv (half)
__device__ __half g_attnh[(size_t)NROWS * DM];        // attention out (half)
__device__ float  g_res1 [(size_t)NROWS * DM];
__device__ __half g_ff   [(size_t)NROWS * DFF];       // gelu out (half)
// transposed (N-major, K-contig) half weights
__device__ __half g_wqkvT[(size_t)3 * DM * DM];
__device__ __half g_woutT[(size_t)DM * DM];
__device__ __half g_wfc1T[(size_t)DFF * DM];
__device__ __half g_wfc2T[(size_t)DM * DFF];

// ---------------- helpers ---------------------------------------------------
__device__ __forceinline__ void cpa16(uint32_t dst, const void* src) {
    asm volatile("cp.async.cg.shared.global [%0], [%1], 16;" :: "r"(dst), "l"(src));
}
#define CP_COMMIT() asm volatile("cp.async.commit_group;" ::: "memory")
#define CP_WAIT(n)  asm volatile("cp.async.wait_group %0;" :: "n"(n) : "memory")

__device__ __forceinline__ uint32_t smem_u32(const void* p) {
    uint32_t a;
    asm("{ .reg .u64 t; cvta.to.shared.u64 t, %1; cvt.u32.u64 %0, t; }" : "=r"(a) : "l"(p));
    return a;
}
__device__ __forceinline__ float gelu_f(float x) {
    float x3 = x * x * x;
    return 0.5f * x * (1.0f + tanhf(0.7978845608028654f * (x + 0.044715f * x3)));
}

#define LDSM4(r0, r1, r2, r3, addr) \
    asm volatile("ldmatrix.sync.aligned.m8n8.x4.shared.b16 {%0,%1,%2,%3}, [%4];" \
        : "=r"(r0), "=r"(r1), "=r"(r2), "=r"(r3) : "r"(addr))
#define LDSM4T(r0, r1, r2, r3, addr) \
    asm volatile("ldmatrix.sync.aligned.m8n8.x4.trans.shared.b16 {%0,%1,%2,%3}, [%4];" \
        : "=r"(r0), "=r"(r1), "=r"(r2), "=r"(r3) : "r"(addr))

#define MMA_F16(c, a0,a1,a2,a3, b0,b1)                                      \
    asm volatile(                                                           \
        "mma.sync.aligned.m16n8k16.row.col.f32.f16.f16.f32 "                \
        "{%0,%1,%2,%3}, {%4,%5,%6,%7}, {%8,%9}, {%0,%1,%2,%3};\n"           \
        : "+f"((c)[0]), "+f"((c)[1]), "+f"((c)[2]), "+f"((c)[3])            \
        : "r"(a0), "r"(a1), "r"(a2), "r"(a3), "r"(b0), "r"(b1))

// ---------------- weight transpose -> half, K-contiguous --------------------
__global__ __launch_bounds__(256) void transpose_h(
    const float* __restrict__ in, __half* __restrict__ out, int K, int N)
{
    __shared__ float s[32 * 33];
    int t = threadIdx.x;
    int n0 = blockIdx.x * 32, k0 = blockIdx.y * 32;
    int r = t >> 3, c = (t & 7) * 4;
    float4 v = *(const float4*)(in + (size_t)(k0 + r) * N + n0 + c);
    s[(c + 0) * 33 + r] = v.x;
    s[(c + 1) * 33 + r] = v.y;
    s[(c + 2) * 33 + r] = v.z;
    s[(c + 3) * 33 + r] = v.w;
    __syncthreads();
    __half2 h0 = __floats2half2_rn(s[r * 33 + c + 0], s[r * 33 + c + 1]);
    __half2 h1 = __floats2half2_rn(s[r * 33 + c + 2], s[r * 33 + c + 3]);
    __half* op = out + (size_t)(n0 + r) * K + k0 + c;
    *(__half2*)(op)     = h0;
    *(__half2*)(op + 2) = h1;
}

// ---------------- LayerNorm (outputs half) ----------------------------------
__global__ __launch_bounds__(256) void ln_kernel(
    const float* __restrict__ x, const float* __restrict__ scale,
    const float* __restrict__ bias, __half* __restrict__ out)
{
    int row = blockIdx.x;
    const float4* xr = (const float4*)(x + (size_t)row * DM);
    float4 v = xr[threadIdx.x];
    float s  = v.x + v.y + v.z + v.w;
    float ss = v.x*v.x + v.y*v.y + v.z*v.z + v.w*v.w;
    #pragma unroll
    for (int o = 16; o > 0; o >>= 1) {
        s  += __shfl_xor_sync(0xffffffffu, s,  o);
        ss += __shfl_xor_sync(0xffffffffu, ss, o);
    }
    __shared__ float smS[8], smSS[8];
    __shared__ float sMean, sRstd;
    int w = threadIdx.x >> 5, lane = threadIdx.x & 31;
    if (lane == 0) { smS[w] = s; smSS[w] = ss; }
    __syncthreads();
    if (threadIdx.x == 0) {
        float S = 0.f, SS = 0.f;
        #pragma unroll
        for (int i = 0; i < 8; i++) { S += smS[i]; SS += smSS[i]; }
        float mean = S * (1.0f / DM);
        float var  = SS * (1.0f / DM) - mean * mean;
        sMean = mean; sRstd = rsqrtf(var + 1e-6f);
    }
    __syncthreads();
    float mean = sMean, rstd = sRstd;
    int c = threadIdx.x * 4;
    float4 sc = *(const float4*)(scale + c);
    float4 bi = *(const float4*)(bias  + c);
    __half2 h0 = __floats2half2_rn((v.x - mean) * rstd * sc.x + bi.x,
                                   (v.y - mean) * rstd * sc.y + bi.y);
    __half2 h1 = __floats2half2_rn((v.z - mean) * rstd * sc.z + bi.z,
                                   (v.w - mean) * rstd * sc.w + bi.w);
    __half* op = out + (size_t)row * DM + c;
    *(__half2*)(op)     = h0;
    *(__half2*)(op + 2) = h1;
}

// ---------------- FP16 mma.sync GEMM: 128x128, 256 thr, 4 stages ------------
// epi: 0 = bias -> half, 1 = bias + residual -> fp32, 2 = gelu(bias) -> half
#define HROWB 80
#define HSTGB (128 * HROWB * 2)        /* 20480 B per stage (A+B) */
#define NSTG  4
#define HGSM  (NSTG * HSTGB)           /* 81920 B */

__global__ __launch_bounds__(256, 2) void gemm_f16(
    const __half* __restrict__ A, const __half* __restrict__ Bt,
    const float* __restrict__ bias, const float* __restrict__ R,
    float* __restrict__ C, __half* __restrict__ Ch,
    int M, int N, int K, int epi)
{
    extern __shared__ char smc[];
    const uint32_t sb = smem_u32(smc);

    const int t  = threadIdx.x;
    const int m0 = blockIdx.y * 128, n0 = blockIdx.x * 128;
    const int w  = t >> 5, lane = t & 31;
    const int wr = w >> 2, wc = w & 3;
    const int wm = wr * 64, wn = wc * 32;
    const int lr = lane >> 2, lc = lane & 3;

    float c[4][4][4];
    #pragma unroll
    for (int mf = 0; mf < 4; mf++)
        #pragma unroll
        for (int nf = 0; nf < 4; nf++)
            #pragma unroll
            for (int i = 0; i < 4; i++) c[mf][nf][i] = 0.f;

    const int row = t >> 2, kg = t & 3;
    const __half* Ap0 = A  + (size_t)(m0 + row)      * K + kg * 8;
    const __half* Ap1 = A  + (size_t)(m0 + 64 + row) * K + kg * 8;
    const __half* Bp0 = Bt + (size_t)(n0 + row)      * K + kg * 8;
    const __half* Bp1 = Bt + (size_t)(n0 + 64 + row) * K + kg * 8;
    const uint32_t dA0 = sb + row * HROWB + kg * 16;
    const uint32_t dA1 = sb + (row + 64) * HROWB + kg * 16;
    const uint32_t dB0 = sb + 10240 + row * HROWB + kg * 16;
    const uint32_t dB1 = sb + 10240 + (row + 64) * HROWB + kg * 16;

    const int NC = K >> 5;

    #define LOAD_STAGE(st, cc) do {                                   \
        uint32_t so_ = (uint32_t)(st) * HSTGB;                        \
        size_t ko_ = (size_t)(cc) << 5;                               \
        cpa16(dA0 + so_, Ap0 + ko_);                                  \
        cpa16(dA1 + so_, Ap1 + ko_);                                  \
        cpa16(dB0 + so_, Bp0 + ko_);                                  \
        cpa16(dB1 + so_, Bp1 + ko_);                                  \
        CP_COMMIT();                                                  \
    } while (0)

    LOAD_STAGE(0, 0);
    LOAD_STAGE(1, 1);
    LOAD_STAGE(2, 2);

    const int lm_r = lane & 15;
    const int lm_k = (lane >> 4) * 16;

    int st = 0;
    for (int cc = 0; cc < NC; cc++) {
        CP_WAIT(2);
        __syncthreads();
        // stage (st+3)%4 was fully consumed in iteration cc-1 (proven by the
        // barrier above) -> refill it now, overlapping cp.async with MMAs.
        if (cc + 3 < NC) LOAD_STAGE((st + 3) & 3, cc + 3);
        else             CP_COMMIT();

        const uint32_t as = sb + st * HSTGB;
        const uint32_t bs = as + 10240;
        #pragma unroll
        for (int ks = 0; ks < 2; ks++) {
            uint32_t af[4][4];
            #pragma unroll
            for (int mf = 0; mf < 4; mf++) {
                uint32_t addr = as + (wm + mf * 16 + lm_r) * HROWB + ks * 32 + lm_k;
                LDSM4(af[mf][0], af[mf][1], af[mf][2], af[mf][3], addr);
            }
            uint32_t bf[4][2];
            #pragma unroll
            for (int np = 0; np < 2; np++) {
                uint32_t r0, r1, r2, r3;
                uint32_t addr = bs + (wn + np * 16 + lm_r) * HROWB + ks * 32 + lm_k;
                LDSM4(r0, r1, r2, r3, addr);
                bf[np * 2 + 0][0] = r0; bf[np * 2 + 0][1] = r2;
                bf[np * 2 + 1][0] = r1; bf[np * 2 + 1][1] = r3;
            }
            #pragma unroll
            for (int mf = 0; mf < 4; mf++)
                #pragma unroll
                for (int nf = 0; nf < 4; nf++)
                    MMA_F16(c[mf][nf], af[mf][0], af[mf][1], af[mf][2], af[mf][3],
                            bf[nf][0], bf[nf][1]);
        }
        st = (st + 1) & 3;
    }
    #undef LOAD_STAGE

    // -------- epilogue --------
    #pragma unroll
    for (int mf = 0; mf < 4; mf++) {
        #pragma unroll
        for (int nf = 0; nf < 4; nf++) {
            int rowg = m0 + wm + mf * 16 + lr;
            int col  = n0 + wn + nf * 8 + lc * 2;
            float b0 = bias[col], b1 = bias[col + 1];
            float v0 = c[mf][nf][0] + b0;
            float v1 = c[mf][nf][1] + b1;
            float v2 = c[mf][nf][2] + b0;
            float v3 = c[mf][nf][3] + b1;
            if (epi == 1) {
                const float* r0 = R + (size_t)rowg * N + col;
                const float* r1 = R + (size_t)(rowg + 8) * N + col;
                v0 += r0[0]; v1 += r0[1];
                v2 += r1[0]; v3 += r1[1];
                *(float2*)(C + (size_t)rowg * N + col)       = make_float2(v0, v1);
                *(float2*)(C + (size_t)(rowg + 8) * N + col) = make_float2(v2, v3);
            } else if (epi == 2) {
                *(__half2*)(Ch + (size_t)rowg * N + col) =
                    __floats2half2_rn(gelu_f(v0), gelu_f(v1));
                *(__half2*)(Ch + (size_t)(rowg + 8) * N + col) =
                    __floats2half2_rn(gelu_f(v2), gelu_f(v3));
            } else {
                *(__half2*)(Ch + (size_t)rowg * N + col) =
                    __floats2half2_rn(v0, v1);
                *(__half2*)(Ch + (size_t)(rowg + 8) * N + col) =
                    __floats2half2_rn(v2, v3);
            }
        }
    }
}

// ---------------- Flash-attention, fp16 mma + ldmatrix (causal) -------------
// BQ=128, BK=64, 8 warps (16 q-rows each).  grid (SEQ/128, BATCH*NHEAD).
// qt reversed (LPT): longest blocks launch first.
#define AH 72
#define ATTN_SM_BYTES ((128*AH + 64*AH + 64*AH + 128*AH) * 2)  /* 55296 */

__global__ __launch_bounds__(256) void attn_f16()
{
    extern __shared__ __half smh[];
    __half* Qs = smh;
    __half* Ks = Qs + 128 * AH;
    __half* Vs = Ks + 64 * AH;
    __half* Ps = Vs + 64 * AH;
    const uint32_t sQ = smem_u32(Qs), sK = smem_u32(Ks),
                   sV = smem_u32(Vs), sP = smem_u32(Ps);

    const int t = threadIdx.x, w = t >> 5, lane = t & 31;
    const int lr = lane >> 2, lc = lane & 3;
    const int lm_r = lane & 15, lm_c = (lane >> 4) * 8;
    const int qt = gridDim.x - 1 - blockIdx.x;      // LPT: big tiles first
    const int bh = blockIdx.y;
    const int b = bh >> 4, h = bh & 15;
    const size_t baseBH = (size_t)b * SEQ * (3 * DM) + (size_t)h * HD;
    const int q0 = qt * 128;
    const int wm = w * 16;

    const __half2 hscale = __floats2half2_rn(0.125f, 0.125f);
    for (int i = t; i < 128 * 8; i += 256) {
        int r = i >> 3, g = i & 7;
        uint4 v = *(const uint4*)&g_qkvh[baseBH + (size_t)(q0 + r) * (3 * DM) + g * 8];
        __half2* hp = (__half2*)&v;
        hp[0] = __hmul2(hp[0], hscale);
        hp[1] = __hmul2(hp[1], hscale);
        hp[2] = __hmul2(hp[2], hscale);
        hp[3] = __hmul2(hp[3], hscale);
        *(uint4*)&Qs[r * AH + g * 8] = v;
    }

    float o[8][4];
    #pragma unroll
    for (int nf = 0; nf < 8; nf++)
        #pragma unroll
        for (int i = 0; i < 4; i++) o[nf][i] = 0.f;
    float m0v = -1e30f, m1v = -1e30f, l0 = 0.f, l1 = 0.f;

    const int ntile = (q0 + 128) / 64;
    for (int kt = 0; kt < ntile; kt++) {
        int k0 = kt * 64;
        for (int i = t; i < 64 * 8; i += 256) {
            int r = i >> 3, g = i & 7;
            size_t base = baseBH + (size_t)(k0 + r) * (3 * DM);
            *(uint4*)&Ks[r * AH + g * 8] = *(const uint4*)&g_qkvh[base + DM + g * 8];
            *(uint4*)&Vs[r * AH + g * 8] = *(const uint4*)&g_qkvh[base + 2 * DM + g * 8];
        }
        __syncthreads();

        float s[8][4];
        #pragma unroll
        for (int nf = 0; nf < 8; nf++)
            #pragma unroll
            for (int i = 0; i < 4; i++) s[nf][i] = 0.f;
        #pragma unroll
        for (int ks = 0; ks < 4; ks++) {
            uint32_t a0, a1, a2, a3;
            LDSM4(a0, a1, a2, a3,
                  sQ + ((wm + lm_r) * AH + ks * 16 + lm_c) * 2);
            #pragma unroll
            for (int np = 0; np < 4; np++) {
                uint32_t r0, r1, r2, r3;
                LDSM4(r0, r1, r2, r3,
                      sK + ((np * 16 + lm_r) * AH + ks * 16 + lm_c) * 2);
                MMA_F16(s[np * 2 + 0], a0, a1, a2, a3, r0, r2);
                MMA_F16(s[np * 2 + 1], a0, a1, a2, a3, r1, r3);
            }
        }

        if (k0 + 63 > q0 + wm) {
            int qi0 = q0 + wm + lr, qi1 = qi0 + 8;
            #pragma unroll
            for (int nf = 0; nf < 8; nf++) {
                int kj0 = k0 + nf * 8 + 2 * lc, kj1 = kj0 + 1;
                if (kj0 > qi0) s[nf][0] = -1e30f;
                if (kj1 > qi0) s[nf][1] = -1e30f;
                if (kj0 > qi1) s[nf][2] = -1e30f;
                if (kj1 > qi1) s[nf][3] = -1e30f;
            }
        }

        float mt0 = -1e30f, mt1 = -1e30f;
        #pragma unroll
        for (int nf = 0; nf < 8; nf++) {
            mt0 = fmaxf(mt0, fmaxf(s[nf][0], s[nf][1]));
            mt1 = fmaxf(mt1, fmaxf(s[nf][2], s[nf][3]));
        }
        mt0 = fmaxf(mt0, __shfl_xor_sync(0xffffffffu, mt0, 1));
        mt0 = fmaxf(mt0, __shfl_xor_sync(0xffffffffu, mt0, 2));
        mt1 = fmaxf(mt1, __shfl_xor_sync(0xffffffffu, mt1, 1));
        mt1 = fmaxf(mt1, __shfl_xor_sync(0xffffffffu, mt1, 2));
        float mn0 = fmaxf(m0v, mt0), mn1 = fmaxf(m1v, mt1);
        float scl0 = __expf(m0v - mn0), scl1 = __expf(m1v - mn1);
        m0v = mn0; m1v = mn1;
        float ls0 = 0.f, ls1 = 0.f;
        #pragma unroll
        for (int nf = 0; nf < 8; nf++) {
            float p0 = __expf(s[nf][0] - mn0);
            float p1 = __expf(s[nf][1] - mn0);
            float p2 = __expf(s[nf][2] - mn1);
            float p3 = __expf(s[nf][3] - mn1);
            s[nf][0] = p0; s[nf][1] = p1; s[nf][2] = p2; s[nf][3] = p3;
            ls0 += p0 + p1; ls1 += p2 + p3;
        }
        ls0 += __shfl_xor_sync(0xffffffffu, ls0, 1);
        ls0 += __shfl_xor_sync(0xffffffffu, ls0, 2);
        ls1 += __shfl_xor_sync(0xffffffffu, ls1, 1);
        ls1 += __shfl_xor_sync(0xffffffffu, ls1, 2);
        l0 = l0 * scl0 + ls0;
        l1 = l1 * scl1 + ls1;
        #pragma unroll
        for (int nf = 0; nf < 8; nf++) {
            o[nf][0] *= scl0; o[nf][1] *= scl0;
            o[nf][2] *= scl1; o[nf][3] *= scl1;
        }

        #pragma unroll
        for (int nf = 0; nf < 8; nf++) {
            *(__half2*)&Ps[(wm + lr) * AH + nf * 8 + 2 * lc] =
                __floats2half2_rn(s[nf][0], s[nf][1]);
            *(__half2*)&Ps[(wm + lr + 8) * AH + nf * 8 + 2 * lc] =
                __floats2half2_rn(s[nf][2], s[nf][3]);
        }
        __syncwarp();

        #pragma unroll
        for (int ks = 0; ks < 4; ks++) {
            uint32_t a0, a1, a2, a3;
            LDSM4(a0, a1, a2, a3,
                  sP + ((wm + lm_r) * AH + ks * 16 + lm_c) * 2);
            #pragma unroll
            for (int dp = 0; dp < 4; dp++) {
                uint32_t r0, r1, r2, r3;
                LDSM4T(r0, r1, r2, r3,
                       sV + ((ks * 16 + lm_r) * AH + dp * 16 + lm_c) * 2);
                MMA_F16(o[dp * 2 + 0], a0, a1, a2, a3, r0, r1);
                MMA_F16(o[dp * 2 + 1], a0, a1, a2, a3, r2, r3);
            }
        }
        __syncthreads();
    }

    float il0 = 1.0f / l0, il1 = 1.0f / l1;
    int row0 = q0 + wm + lr, row1 = row0 + 8;
    #pragma unroll
    for (int nf = 0; nf < 8; nf++) {
        int col = h * HD + nf * 8 + 2 * lc;
        *(__half2*)&g_attnh[(size_t)(b * SEQ + row0) * DM + col] =
            __floats2half2_rn(o[nf][0] * il0, o[nf][1] * il0);
        *(__half2*)&g_attnh[(size_t)(b * SEQ + row1) * DM + col] =
            __floats2half2_rn(o[nf][2] * il1, o[nf][3] * il1);
    }
}

// ---------------- launch ---------------------------------------------------
extern "C" void kernel_launch(void* const* d_in, const int* in_sizes, int n_in,
                              void* d_out, int out_size)
{
    (void)in_sizes; (void)n_in; (void)out_size;
    const float* x     = (const float*)d_in[0];
    const float* w_qkv = (const float*)d_in[1];
    const float* b_qkv = (const float*)d_in[2];
    const float* w_out = (const float*)d_in[3];
    const float* b_out = (const float*)d_in[4];
    const float* w_fc1 = (const float*)d_in[5];
    const float* b_fc1 = (const float*)d_in[6];
    const float* w_fc2 = (const float*)d_in[7];
    const float* b_fc2 = (const float*)d_in[8];
    const float* ln1s  = (const float*)d_in[9];
    const float* ln1b  = (const float*)d_in[10];
    const float* ln2s  = (const float*)d_in[11];
    const float* ln2b  = (const float*)d_in[12];
    float* out = (float*)d_out;

    __half *xn, *qkvh, *attnh, *ff, *wqkvT, *woutT, *wfc1T, *wfc2T;
    float *res1;
    cudaGetSymbolAddress((void**)&xn,    g_xn);
    cudaGetSymbolAddress((void**)&qkvh,  g_qkvh);
    cudaGetSymbolAddress((void**)&attnh, g_attnh);
    cudaGetSymbolAddress((void**)&res1,  g_res1);
    cudaGetSymbolAddress((void**)&ff,    g_ff);
    cudaGetSymbolAddress((void**)&wqkvT, g_wqkvT);
    cudaGetSymbolAddress((void**)&woutT, g_woutT);
    cudaGetSymbolAddress((void**)&wfc1T, g_wfc1T);
    cudaGetSymbolAddress((void**)&wfc2T, g_wfc2T);

    cudaFuncSetAttribute(gemm_f16,
        cudaFuncAttributeMaxDynamicSharedMemorySize, HGSM);
    cudaFuncSetAttribute(attn_f16,
        cudaFuncAttributeMaxDynamicSharedMemorySize, ATTN_SM_BYTES);

    // 0. weight transposes (half, K-contiguous)
    transpose_h<<<dim3(3 * DM / 32, DM / 32), 256>>>(w_qkv, wqkvT, DM, 3 * DM);
    transpose_h<<<dim3(DM / 32, DM / 32), 256>>>(w_out, woutT, DM, DM);
    transpose_h<<<dim3(DFF / 32, DM / 32), 256>>>(w_fc1, wfc1T, DM, DFF);
    transpose_h<<<dim3(DM / 32, DFF / 32), 256>>>(w_fc2, wfc2T, DFF, DM);

    // 1. LN1 -> half
    ln_kernel<<<NROWS, 256>>>(x, ln1s, ln1b, xn);
    // 2. QKV projection -> half
    gemm_f16<<<dim3(3 * DM / 128, NROWS / 128), 256, HGSM>>>(
        xn, wqkvT, b_qkv, (const float*)0, (float*)0, qkvh,
        NROWS, 3 * DM, DM, 0);
    // 3. causal flash attention (fp16 mma) -> half
    attn_f16<<<dim3(SEQ / 128, BATCH * NHEAD), 256, ATTN_SM_BYTES>>>();
    // 4. out projection + residual(x) -> fp32
    gemm_f16<<<dim3(DM / 128, NROWS / 128), 256, HGSM>>>(
        attnh, woutT, b_out, x, res1, (__half*)0, NROWS, DM, DM, 1);
    // 5. LN2 -> half
    ln_kernel<<<NROWS, 256>>>(res1, ln2s, ln2b, xn);
    // 6. FC1 + gelu -> half
    gemm_f16<<<dim3(DFF / 128, NROWS / 128), 256, HGSM>>>(
        xn, wfc1T, b_fc1, (const float*)0, (float*)0, ff, NROWS, DFF, DM, 2);
    // 7. FC2 + residual(res1) -> fp32 out
    gemm_f16<<<dim3(DM / 128, NROWS / 128), 256, HGSM>>>(
        ff, wfc2T, b_fc2, res1, out, (__half*)0, NROWS, DM, DFF, 1);
}

// round 17
// speedup vs baseline: 1.0713x; 1.0206x over previous
#include <cuda_runtime.h>
#include <cuda_fp16.h>
#include <math.h>
#include <stdint.h>

#define BATCH 4
#define SEQ   2048
#define DM    1024
#define DFF   4096
#define NHEAD 16
#define HD    64
#define NROWS (BATCH*SEQ)   /* 8192 */

// ---------------- scratch (device globals; no allocation allowed) ----------
__device__ __half g_xn   [(size_t)NROWS * DM];        // LN out (half)
__device__ __half g_qkvh [(size_t)NROWS * 3 * DM];    // qkv (half)
__device__ __half g_attnh[(size_t)NROWS * DM];        // attention out (half)
__device__ float  g_res1 [(size_t)NROWS * DM];
__device__ __half g_ff   [(size_t)NROWS * DFF];       // gelu out (half)
// transposed (N-major, K-contig) half weights
__device__ __half g_wqkvT[(size_t)3 * DM * DM];
__device__ __half g_woutT[(size_t)DM * DM];
__device__ __half g_wfc1T[(size_t)DFF * DM];
__device__ __half g_wfc2T[(size_t)DM * DFF];

// ---------------- helpers ---------------------------------------------------
__device__ __forceinline__ void cpa16(uint32_t dst, const void* src) {
    asm volatile("cp.async.cg.shared.global [%0], [%1], 16;" :: "r"(dst), "l"(src));
}
#define CP_COMMIT() asm volatile("cp.async.commit_group;" ::: "memory")
#define CP_WAIT(n)  asm volatile("cp.async.wait_group %0;" :: "n"(n) : "memory")

__device__ __forceinline__ uint32_t smem_u32(const void* p) {
    uint32_t a;
    asm("{ .reg .u64 t; cvta.to.shared.u64 t, %1; cvt.u32.u64 %0, t; }" : "=r"(a) : "l"(p));
    return a;
}
__device__ __forceinline__ float gelu_f(float x) {
    float x3 = x * x * x;
    return 0.5f * x * (1.0f + tanhf(0.7978845608028654f * (x + 0.044715f * x3)));
}

#define LDSM4(r0, r1, r2, r3, addr) \
    asm volatile("ldmatrix.sync.aligned.m8n8.x4.shared.b16 {%0,%1,%2,%3}, [%4];" \
        : "=r"(r0), "=r"(r1), "=r"(r2), "=r"(r3) : "r"(addr))
#define LDSM4T(r0, r1, r2, r3, addr) \
    asm volatile("ldmatrix.sync.aligned.m8n8.x4.trans.shared.b16 {%0,%1,%2,%3}, [%4];" \
        : "=r"(r0), "=r"(r1), "=r"(r2), "=r"(r3) : "r"(addr))

#define MMA_F16(c, a0,a1,a2,a3, b0,b1)                                      \
    asm volatile(                                                           \
        "mma.sync.aligned.m16n8k16.row.col.f32.f16.f16.f32 "                \
        "{%0,%1,%2,%3}, {%4,%5,%6,%7}, {%8,%9}, {%0,%1,%2,%3};\n"           \
        : "+f"((c)[0]), "+f"((c)[1]), "+f"((c)[2]), "+f"((c)[3])            \
        : "r"(a0), "r"(a1), "r"(a2), "r"(a3), "r"(b0), "r"(b1))

// ---------------- weight transpose -> half, K-contiguous --------------------
__global__ __launch_bounds__(256) void transpose_h(
    const float* __restrict__ in, __half* __restrict__ out, int K, int N)
{
    __shared__ float s[32 * 33];
    int t = threadIdx.x;
    int n0 = blockIdx.x * 32, k0 = blockIdx.y * 32;
    int r = t >> 3, c = (t & 7) * 4;
    float4 v = *(const float4*)(in + (size_t)(k0 + r) * N + n0 + c);
    s[(c + 0) * 33 + r] = v.x;
    s[(c + 1) * 33 + r] = v.y;
    s[(c + 2) * 33 + r] = v.z;
    s[(c + 3) * 33 + r] = v.w;
    __syncthreads();
    __half2 h0 = __floats2half2_rn(s[r * 33 + c + 0], s[r * 33 + c + 1]);
    __half2 h1 = __floats2half2_rn(s[r * 33 + c + 2], s[r * 33 + c + 3]);
    __half* op = out + (size_t)(n0 + r) * K + k0 + c;
    *(__half2*)(op)     = h0;
    *(__half2*)(op + 2) = h1;
}

// ---------------- LayerNorm (outputs half) ----------------------------------
__global__ __launch_bounds__(256) void ln_kernel(
    const float* __restrict__ x, const float* __restrict__ scale,
    const float* __restrict__ bias, __half* __restrict__ out)
{
    int row = blockIdx.x;
    const float4* xr = (const float4*)(x + (size_t)row * DM);
    float4 v = xr[threadIdx.x];
    float s  = v.x + v.y + v.z + v.w;
    float ss = v.x*v.x + v.y*v.y + v.z*v.z + v.w*v.w;
    #pragma unroll
    for (int o = 16; o > 0; o >>= 1) {
        s  += __shfl_xor_sync(0xffffffffu, s,  o);
        ss += __shfl_xor_sync(0xffffffffu, ss, o);
    }
    __shared__ float smS[8], smSS[8];
    __shared__ float sMean, sRstd;
    int w = threadIdx.x >> 5, lane = threadIdx.x & 31;
    if (lane == 0) { smS[w] = s; smSS[w] = ss; }
    __syncthreads();
    if (threadIdx.x == 0) {
        float S = 0.f, SS = 0.f;
        #pragma unroll
        for (int i = 0; i < 8; i++) { S += smS[i]; SS += smSS[i]; }
        float mean = S * (1.0f / DM);
        float var  = SS * (1.0f / DM) - mean * mean;
        sMean = mean; sRstd = rsqrtf(var + 1e-6f);
    }
    __syncthreads();
    float mean = sMean, rstd = sRstd;
    int c = threadIdx.x * 4;
    float4 sc = *(const float4*)(scale + c);
    float4 bi = *(const float4*)(bias  + c);
    __half2 h0 = __floats2half2_rn((v.x - mean) * rstd * sc.x + bi.x,
                                   (v.y - mean) * rstd * sc.y + bi.y);
    __half2 h1 = __floats2half2_rn((v.z - mean) * rstd * sc.z + bi.z,
                                   (v.w - mean) * rstd * sc.w + bi.w);
    __half* op = out + (size_t)row * DM + c;
    *(__half2*)(op)     = h0;
    *(__half2*)(op + 2) = h1;
}

// ---------------- FP16 mma.sync GEMM: 128x128, 256 thr, 4 stages ------------
// (unchanged from R16 anchor)
#define HROWB 80
#define HSTGB (128 * HROWB * 2)        /* 20480 B per stage (A+B) */
#define NSTG  4
#define HGSM  (NSTG * HSTGB)           /* 81920 B */

__global__ __launch_bounds__(256, 2) void gemm_f16(
    const __half* __restrict__ A, const __half* __restrict__ Bt,
    const float* __restrict__ bias, const float* __restrict__ R,
    float* __restrict__ C, __half* __restrict__ Ch,
    int M, int N, int K, int epi)
{
    extern __shared__ char smc[];
    const uint32_t sb = smem_u32(smc);

    const int t  = threadIdx.x;
    const int m0 = blockIdx.y * 128, n0 = blockIdx.x * 128;
    const int w  = t >> 5, lane = t & 31;
    const int wr = w >> 2, wc = w & 3;
    const int wm = wr * 64, wn = wc * 32;
    const int lr = lane >> 2, lc = lane & 3;

    float c[4][4][4];
    #pragma unroll
    for (int mf = 0; mf < 4; mf++)
        #pragma unroll
        for (int nf = 0; nf < 4; nf++)
            #pragma unroll
            for (int i = 0; i < 4; i++) c[mf][nf][i] = 0.f;

    const int row = t >> 2, kg = t & 3;
    const __half* Ap0 = A  + (size_t)(m0 + row)      * K + kg * 8;
    const __half* Ap1 = A  + (size_t)(m0 + 64 + row) * K + kg * 8;
    const __half* Bp0 = Bt + (size_t)(n0 + row)      * K + kg * 8;
    const __half* Bp1 = Bt + (size_t)(n0 + 64 + row) * K + kg * 8;
    const uint32_t dA0 = sb + row * HROWB + kg * 16;
    const uint32_t dA1 = sb + (row + 64) * HROWB + kg * 16;
    const uint32_t dB0 = sb + 10240 + row * HROWB + kg * 16;
    const uint32_t dB1 = sb + 10240 + (row + 64) * HROWB + kg * 16;

    const int NC = K >> 5;

    #define LOAD_STAGE(st, cc) do {                                   \
        uint32_t so_ = (uint32_t)(st) * HSTGB;                        \
        size_t ko_ = (size_t)(cc) << 5;                               \
        cpa16(dA0 + so_, Ap0 + ko_);                                  \
        cpa16(dA1 + so_, Ap1 + ko_);                                  \
        cpa16(dB0 + so_, Bp0 + ko_);                                  \
        cpa16(dB1 + so_, Bp1 + ko_);                                  \
        CP_COMMIT();                                                  \
    } while (0)

    LOAD_STAGE(0, 0);
    LOAD_STAGE(1, 1);
    LOAD_STAGE(2, 2);

    const int lm_r = lane & 15;
    const int lm_k = (lane >> 4) * 16;

    int st = 0;
    for (int cc = 0; cc < NC; cc++) {
        CP_WAIT(2);
        __syncthreads();
        if (cc + 3 < NC) LOAD_STAGE((st + 3) & 3, cc + 3);
        else             CP_COMMIT();

        const uint32_t as = sb + st * HSTGB;
        const uint32_t bs = as + 10240;
        #pragma unroll
        for (int ks = 0; ks < 2; ks++) {
            uint32_t af[4][4];
            #pragma unroll
            for (int mf = 0; mf < 4; mf++) {
                uint32_t addr = as + (wm + mf * 16 + lm_r) * HROWB + ks * 32 + lm_k;
                LDSM4(af[mf][0], af[mf][1], af[mf][2], af[mf][3], addr);
            }
            uint32_t bf[4][2];
            #pragma unroll
            for (int np = 0; np < 2; np++) {
                uint32_t r0, r1, r2, r3;
                uint32_t addr = bs + (wn + np * 16 + lm_r) * HROWB + ks * 32 + lm_k;
                LDSM4(r0, r1, r2, r3, addr);
                bf[np * 2 + 0][0] = r0; bf[np * 2 + 0][1] = r2;
                bf[np * 2 + 1][0] = r1; bf[np * 2 + 1][1] = r3;
            }
            #pragma unroll
            for (int mf = 0; mf < 4; mf++)
                #pragma unroll
                for (int nf = 0; nf < 4; nf++)
                    MMA_F16(c[mf][nf], af[mf][0], af[mf][1], af[mf][2], af[mf][3],
                            bf[nf][0], bf[nf][1]);
        }
        st = (st + 1) & 3;
    }
    #undef LOAD_STAGE

    // -------- epilogue --------
    #pragma unroll
    for (int mf = 0; mf < 4; mf++) {
        #pragma unroll
        for (int nf = 0; nf < 4; nf++) {
            int rowg = m0 + wm + mf * 16 + lr;
            int col  = n0 + wn + nf * 8 + lc * 2;
            float b0 = bias[col], b1 = bias[col + 1];
            float v0 = c[mf][nf][0] + b0;
            float v1 = c[mf][nf][1] + b1;
            float v2 = c[mf][nf][2] + b0;
            float v3 = c[mf][nf][3] + b1;
            if (epi == 1) {
                const float* r0 = R + (size_t)rowg * N + col;
                const float* r1 = R + (size_t)(rowg + 8) * N + col;
                v0 += r0[0]; v1 += r0[1];
                v2 += r1[0]; v3 += r1[1];
                *(float2*)(C + (size_t)rowg * N + col)       = make_float2(v0, v1);
                *(float2*)(C + (size_t)(rowg + 8) * N + col) = make_float2(v2, v3);
            } else if (epi == 2) {
                *(__half2*)(Ch + (size_t)rowg * N + col) =
                    __floats2half2_rn(gelu_f(v0), gelu_f(v1));
                *(__half2*)(Ch + (size_t)(rowg + 8) * N + col) =
                    __floats2half2_rn(gelu_f(v2), gelu_f(v3));
            } else {
                *(__half2*)(Ch + (size_t)rowg * N + col) =
                    __floats2half2_rn(v0, v1);
                *(__half2*)(Ch + (size_t)(rowg + 8) * N + col) =
                    __floats2half2_rn(v2, v3);
            }
        }
    }
}

// ---------------- Flash-attention, fp16 mma + cp.async double buffer --------
// BQ=128, BK=64 x2 buffers, 8 warps.  grid (SEQ/128, BATCH*NHEAD), LPT order.
// smem: Q[128][AH] + K[2][64][AH] + V[2][64][AH] + P[128][AH]
#define AH 72   /* 144 B rows, 16B-aligned for cp.async, ldmatrix conflict-free */
#define ATTN_SM_BYTES ((128 + 2*64 + 2*64 + 128) * AH * 2)   /* 73728 */

__global__ __launch_bounds__(256) void attn_f16()
{
    extern __shared__ __half smh[];
    __half* Qs = smh;                       // [128][AH]
    __half* Kb = Qs + 128 * AH;             // [2][64][AH]
    __half* Vb = Kb + 2 * 64 * AH;          // [2][64][AH]
    __half* Ps = Vb + 2 * 64 * AH;          // [128][AH]
    const uint32_t sQ = smem_u32(Qs), sKb = smem_u32(Kb),
                   sVb = smem_u32(Vb), sP = smem_u32(Ps);

    const int t = threadIdx.x, w = t >> 5, lane = t & 31;
    const int lr = lane >> 2, lc = lane & 3;
    const int lm_r = lane & 15, lm_c = (lane >> 4) * 8;
    const int qt = gridDim.x - 1 - blockIdx.x;      // LPT: big tiles first
    const int bh = blockIdx.y;
    const int b = bh >> 4, h = bh & 15;
    const size_t baseBH = (size_t)b * SEQ * (3 * DM) + (size_t)h * HD;
    const int q0 = qt * 128;
    const int wm = w * 16;

    // prologue: Q raw via cp.async (scale folded into softmax)
    {
        #pragma unroll
        for (int i = 0; i < 4; i++) {
            int idx = t + i * 256;          // 1024 granules: 128 rows x 8
            int r = idx >> 3, g = idx & 7;
            cpa16(sQ + (r * AH + g * 8) * 2,
                  &g_qkvh[baseBH + (size_t)(q0 + r) * (3 * DM) + g * 8]);
        }
        CP_COMMIT();
    }
    // K/V tile loader: 512 granules each (64 rows x 8) -> 2 per thread per array
    #define LOAD_KV(buf, kt_) do {                                            \
        uint32_t kd_ = sKb + (uint32_t)(buf) * (64 * AH * 2);                 \
        uint32_t vd_ = sVb + (uint32_t)(buf) * (64 * AH * 2);                 \
        int k0_ = (kt_) * 64;                                                 \
        _Pragma("unroll")                                                     \
        for (int i_ = 0; i_ < 2; i_++) {                                      \
            int idx_ = t + i_ * 256;                                          \
            int r_ = idx_ >> 3, g_ = idx_ & 7;                                \
            size_t base_ = baseBH + (size_t)(k0_ + r_) * (3 * DM) + g_ * 8;   \
            cpa16(kd_ + (r_ * AH + g_ * 8) * 2, &g_qkvh[base_ + DM]);         \
            cpa16(vd_ + (r_ * AH + g_ * 8) * 2, &g_qkvh[base_ + 2 * DM]);     \
        }                                                                     \
        CP_COMMIT();                                                          \
    } while (0)

    LOAD_KV(0, 0);

    float o[8][4];
    #pragma unroll
    for (int nf = 0; nf < 8; nf++)
        #pragma unroll
        for (int i = 0; i < 4; i++) o[nf][i] = 0.f;
    float m0v = -1e30f, m1v = -1e30f, l0 = 0.f, l1 = 0.f;

    const int ntile = (q0 + 128) / 64;
    for (int kt = 0; kt < ntile; kt++) {
        CP_WAIT(0);
        __syncthreads();   // tile kt resident; all warps done with buffer (kt+1)&1
        if (kt + 1 < ntile) LOAD_KV((kt + 1) & 1, kt + 1);

        const uint32_t sK = sKb + (uint32_t)(kt & 1) * (64 * AH * 2);
        const uint32_t sV = sVb + (uint32_t)(kt & 1) * (64 * AH * 2);
        const int k0 = kt * 64;

        // ---- S = Q @ K^T ----
        float s[8][4];
        #pragma unroll
        for (int nf = 0; nf < 8; nf++)
            #pragma unroll
            for (int i = 0; i < 4; i++) s[nf][i] = 0.f;
        #pragma unroll
        for (int ks = 0; ks < 4; ks++) {
            uint32_t a0, a1, a2, a3;
            LDSM4(a0, a1, a2, a3,
                  sQ + ((wm + lm_r) * AH + ks * 16 + lm_c) * 2);
            #pragma unroll
            for (int np = 0; np < 4; np++) {
                uint32_t r0, r1, r2, r3;
                LDSM4(r0, r1, r2, r3,
                      sK + ((np * 16 + lm_r) * AH + ks * 16 + lm_c) * 2);
                MMA_F16(s[np * 2 + 0], a0, a1, a2, a3, r0, r2);
                MMA_F16(s[np * 2 + 1], a0, a1, a2, a3, r1, r3);
            }
        }
        // fold 1/sqrt(64) scale here (exp invariant wrt ordering; 0.125 exact)
        #pragma unroll
        for (int nf = 0; nf < 8; nf++) {
            s[nf][0] *= 0.125f; s[nf][1] *= 0.125f;
            s[nf][2] *= 0.125f; s[nf][3] *= 0.125f;
        }

        if (k0 + 63 > q0 + wm) {
            int qi0 = q0 + wm + lr, qi1 = qi0 + 8;
            #pragma unroll
            for (int nf = 0; nf < 8; nf++) {
                int kj0 = k0 + nf * 8 + 2 * lc, kj1 = kj0 + 1;
                if (kj0 > qi0) s[nf][0] = -1e30f;
                if (kj1 > qi0) s[nf][1] = -1e30f;
                if (kj0 > qi1) s[nf][2] = -1e30f;
                if (kj1 > qi1) s[nf][3] = -1e30f;
            }
        }

        // ---- online softmax in registers ----
        float mt0 = -1e30f, mt1 = -1e30f;
        #pragma unroll
        for (int nf = 0; nf < 8; nf++) {
            mt0 = fmaxf(mt0, fmaxf(s[nf][0], s[nf][1]));
            mt1 = fmaxf(mt1, fmaxf(s[nf][2], s[nf][3]));
        }
        mt0 = fmaxf(mt0, __shfl_xor_sync(0xffffffffu, mt0, 1));
        mt0 = fmaxf(mt0, __shfl_xor_sync(0xffffffffu, mt0, 2));
        mt1 = fmaxf(mt1, __shfl_xor_sync(0xffffffffu, mt1, 1));
        mt1 = fmaxf(mt1, __shfl_xor_sync(0xffffffffu, mt1, 2));
        float mn0 = fmaxf(m0v, mt0), mn1 = fmaxf(m1v, mt1);
        float scl0 = __expf(m0v - mn0), scl1 = __expf(m1v - mn1);
        m0v = mn0; m1v = mn1;
        float ls0 = 0.f, ls1 = 0.f;
        #pragma unroll
        for (int nf = 0; nf < 8; nf++) {
            float p0 = __expf(s[nf][0] - mn0);
            float p1 = __expf(s[nf][1] - mn0);
            float p2 = __expf(s[nf][2] - mn1);
            float p3 = __expf(s[nf][3] - mn1);
            s[nf][0] = p0; s[nf][1] = p1; s[nf][2] = p2; s[nf][3] = p3;
            ls0 += p0 + p1; ls1 += p2 + p3;
        }
        ls0 += __shfl_xor_sync(0xffffffffu, ls0, 1);
        ls0 += __shfl_xor_sync(0xffffffffu, ls0, 2);
        ls1 += __shfl_xor_sync(0xffffffffu, ls1, 1);
        ls1 += __shfl_xor_sync(0xffffffffu, ls1, 2);
        l0 = l0 * scl0 + ls0;
        l1 = l1 * scl1 + ls1;
        #pragma unroll
        for (int nf = 0; nf < 8; nf++) {
            o[nf][0] *= scl0; o[nf][1] *= scl0;
            o[nf][2] *= scl1; o[nf][3] *= scl1;
        }

        // ---- P (half) -> per-warp smem slice ----
        #pragma unroll
        for (int nf = 0; nf < 8; nf++) {
            *(__half2*)&Ps[(wm + lr) * AH + nf * 8 + 2 * lc] =
                __floats2half2_rn(s[nf][0], s[nf][1]);
            *(__half2*)&Ps[(wm + lr + 8) * AH + nf * 8 + 2 * lc] =
                __floats2half2_rn(s[nf][2], s[nf][3]);
        }
        __syncwarp();

        // ---- O += P @ V ----
        #pragma unroll
        for (int ks = 0; ks < 4; ks++) {
            uint32_t a0, a1, a2, a3;
            LDSM4(a0, a1, a2, a3,
                  sP + ((wm + lm_r) * AH + ks * 16 + lm_c) * 2);
            #pragma unroll
            for (int dp = 0; dp < 4; dp++) {
                uint32_t r0, r1, r2, r3;
                LDSM4T(r0, r1, r2, r3,
                       sV + ((ks * 16 + lm_r) * AH + dp * 16 + lm_c) * 2);
                MMA_F16(o[dp * 2 + 0], a0, a1, a2, a3, r0, r1);
                MMA_F16(o[dp * 2 + 1], a0, a1, a2, a3, r2, r3);
            }
        }
        // no trailing barrier: next iteration's barrier (after CP_WAIT) protects
        // the buffer that the following LOAD_KV overwrites.
    }
    #undef LOAD_KV

    float il0 = 1.0f / l0, il1 = 1.0f / l1;
    int row0 = q0 + wm + lr, row1 = row0 + 8;
    #pragma unroll
    for (int nf = 0; nf < 8; nf++) {
        int col = h * HD + nf * 8 + 2 * lc;
        *(__half2*)&g_attnh[(size_t)(b * SEQ + row0) * DM + col] =
            __floats2half2_rn(o[nf][0] * il0, o[nf][1] * il0);
        *(__half2*)&g_attnh[(size_t)(b * SEQ + row1) * DM + col] =
            __floats2half2_rn(o[nf][2] * il1, o[nf][3] * il1);
    }
}

// ---------------- launch ---------------------------------------------------
extern "C" void kernel_launch(void* const* d_in, const int* in_sizes, int n_in,
                              void* d_out, int out_size)
{
    (void)in_sizes; (void)n_in; (void)out_size;
    const float* x     = (const float*)d_in[0];
    const float* w_qkv = (const float*)d_in[1];
    const float* b_qkv = (const float*)d_in[2];
    const float* w_out = (const float*)d_in[3];
    const float* b_out = (const float*)d_in[4];
    const float* w_fc1 = (const float*)d_in[5];
    const float* b_fc1 = (const float*)d_in[6];
    const float* w_fc2 = (const float*)d_in[7];
    const float* b_fc2 = (const float*)d_in[8];
    const float* ln1s  = (const float*)d_in[9];
    const float* ln1b  = (const float*)d_in[10];
    const float* ln2s  = (const float*)d_in[11];
    const float* ln2b  = (const float*)d_in[12];
    float* out = (float*)d_out;

    __half *xn, *qkvh, *attnh, *ff, *wqkvT, *woutT, *wfc1T, *wfc2T;
    float *res1;
    cudaGetSymbolAddress((void**)&xn,    g_xn);
    cudaGetSymbolAddress((void**)&qkvh,  g_qkvh);
    cudaGetSymbolAddress((void**)&attnh, g_attnh);
    cudaGetSymbolAddress((void**)&res1,  g_res1);
    cudaGetSymbolAddress((void**)&ff,    g_ff);
    cudaGetSymbolAddress((void**)&wqkvT, g_wqkvT);
    cudaGetSymbolAddress((void**)&woutT, g_woutT);
    cudaGetSymbolAddress((void**)&wfc1T, g_wfc1T);
    cudaGetSymbolAddress((void**)&wfc2T, g_wfc2T);

    cudaFuncSetAttribute(gemm_f16,
        cudaFuncAttributeMaxDynamicSharedMemorySize, HGSM);
    cudaFuncSetAttribute(attn_f16,
        cudaFuncAttributeMaxDynamicSharedMemorySize, ATTN_SM_BYTES);

    // 0. weight transposes (half, K-contiguous)
    transpose_h<<<dim3(3 * DM / 32, DM / 32), 256>>>(w_qkv, wqkvT, DM, 3 * DM);
    transpose_h<<<dim3(DM / 32, DM / 32), 256>>>(w_out, woutT, DM, DM);
    transpose_h<<<dim3(DFF / 32, DM / 32), 256>>>(w_fc1, wfc1T, DM, DFF);
    transpose_h<<<dim3(DM / 32, DFF / 32), 256>>>(w_fc2, wfc2T, DFF, DM);

    // 1. LN1 -> half
    ln_kernel<<<NROWS, 256>>>(x, ln1s, ln1b, xn);
    // 2. QKV projection -> half
    gemm_f16<<<dim3(3 * DM / 128, NROWS / 128), 256, HGSM>>>(
        xn, wqkvT, b_qkv, (const float*)0, (float*)0, qkvh,
        NROWS, 3 * DM, DM, 0);
    // 3. causal flash attention (fp16 mma, cp.async pipelined) -> half
    attn_f16<<<dim3(SEQ / 128, BATCH * NHEAD), 256, ATTN_SM_BYTES>>>();
    // 4. out projection + residual(x) -> fp32
    gemm_f16<<<dim3(DM / 128, NROWS / 128), 256, HGSM>>>(
        attnh, woutT, b_out, x, res1, (__half*)0, NROWS, DM, DM, 1);
    // 5. LN2 -> half
    ln_kernel<<<NROWS, 256>>>(res1, ln2s, ln2b, xn);
    // 6. FC1 + gelu -> half
    gemm_f16<<<dim3(DFF / 128, NROWS / 128), 256, HGSM>>>(
        xn, wfc1T, b_fc1, (const float*)0, (float*)0, ff, NROWS, DFF, DM, 2);
    // 7. FC2 + residual(res1) -> fp32 out
    gemm_f16<<<dim3(DM / 128, NROWS / 128), 256, HGSM>>>(
        ff, wfc2T, b_fc2, res1, out, (__half*)0, NROWS, DM, DFF, 1);
}